// round 10
// baseline (speedup 1.0000x reference)
#include <cuda_runtime.h>
#include <cuda_bf16.h>
#include <cstdint>

// Problem constants: B=256, IN=64, HID=128, OUT=64, T=1000
// Output: ys (B,T,64) then hs (B,T,128), float32.

// ------------------------- device scratch (no allocs allowed) --------------
__device__ float g_ximp[256 * 64 * 1000];                 // imputed x (B,IN,T)
__device__ float g_pre[131072000];                        // (B,T,[gamH,preZ,preR,preH],128)

// ------------------------- helpers -----------------------------------------
__device__ __forceinline__ void fma2(unsigned long long& d, unsigned long long a,
                                     unsigned long long b) {
    asm("fma.rn.f32x2 %0, %1, %2, %0;" : "+l"(d) : "l"(a), "l"(b));
}
__device__ __forceinline__ unsigned long long pk2(float lo, float hi) {
    unsigned long long r;
    asm("mov.b64 %0, {%1, %2};" : "=l"(r) : "f"(lo), "f"(hi));
    return r;
}
__device__ __forceinline__ float2 up2(unsigned long long v) {
    float2 r;
    asm("mov.b64 {%0, %1}, %2;" : "=f"(r.x), "=f"(r.y) : "l"(v));
    return r;
}
__device__ __forceinline__ float sigf(float x) { return 1.f / (1.f + __expf(-x)); }
__device__ __forceinline__ float tanhf_(float x) { return 1.f - 2.f / (1.f + __expf(2.f * x)); }

// ============================================================================
// K1: imputation. One CTA per batch. gamma_x GEMM + LOCF scan + impute.
// ============================================================================
__global__ void __launch_bounds__(256) k1_impute(
    const float* __restrict__ inp, const float* __restrict__ xmean,
    const float* __restrict__ Wdgx, const float* __restrict__ bdgx)
{
    extern __shared__ float sm_[];
    float* sx  = sm_;                 // 64 x 129
    float* smk = sx + 64 * 129;
    float* sd  = smk + 64 * 129;
    float* sg  = sd + 64 * 129;
    float* sW  = sg + 64 * 129;       // 64 x 64
    const int b = blockIdx.x, tid = threadIdx.x;

    for (int e = tid; e < 64 * 64; e += 256) sW[e] = Wdgx[e];
    float xl  = 0.f;
    float xmn = (tid < 64) ? xmean[tid] : 0.f;

    for (int t0 = 0; t0 < 1000; t0 += 128) {
        const int nv = min(128, 1000 - t0);
        __syncthreads();
        for (int e = tid; e < 64 * 128; e += 256) {
            int i = e >> 7, u = e & 127;
            float xv = 0.f, mv = 0.f, dv = 0.f;
            if (u < nv) {
                size_t gb = ((size_t)(b * 3 * 64) + i) * 1000 + t0 + u;
                xv = inp[gb];
                mv = inp[gb + 64 * 1000];
                dv = inp[gb + 2 * 64 * 1000];
            }
            sx[i * 129 + u] = xv; smk[i * 129 + u] = mv; sd[i * 129 + u] = dv;
        }
        __syncthreads();
        // gamma_x = exp(-relu(d @ W_dg_x + b_dg_x))
        for (int e = tid; e < 64 * 128; e += 256) {
            int j = e >> 7, u = e & 127;
            float acc = bdgx[j];
            #pragma unroll 8
            for (int k = 0; k < 64; k++) acc += sd[k * 129 + u] * sW[k * 64 + j];
            sg[j * 129 + u] = __expf(-fmaxf(acc, 0.f));
        }
        __syncthreads();
        if (tid < 64) {
            const int i = tid;
            for (int u = 0; u < nv; u++) {
                float mv = smk[i * 129 + u], xv = sx[i * 129 + u], gv = sg[i * 129 + u];
                if (mv > 0.f) xl = xv;
                sx[i * 129 + u] = mv * xv + (1.f - mv) * (gv * xl + (1.f - gv) * xmn);
            }
        }
        __syncthreads();
        for (int e = tid; e < 64 * 128; e += 256) {
            int i = e >> 7, u = e & 127;
            if (u < nv) g_ximp[((size_t)(b * 64) + i) * 1000 + t0 + u] = sx[i * 129 + u];
        }
    }
}

// ============================================================================
// K2: pre-activations. CTA = (t-tile 64, batch). f32x2 packed over t-pairs.
// ============================================================================
__device__ __forceinline__ void gemm64(const float* __restrict__ s,
                                       const float* __restrict__ sW,
                                       unsigned long long acc[16], int h, int base)
{
    #pragma unroll 4
    for (int k = 0; k < 64; k++) {
        float w = sW[k * 128 + h];
        unsigned long long w2 = pk2(w, w);
        const ulonglong2* row = (const ulonglong2*)(s + k * 64 + base);
        #pragma unroll
        for (int j = 0; j < 8; j++) {
            ulonglong2 v = row[j];
            fma2(acc[2 * j],     v.x, w2);
            fma2(acc[2 * j + 1], v.y, w2);
        }
    }
}

__device__ __forceinline__ void store_pre(const unsigned long long acc[16],
                                          int b, int t0, int base, int h, int c, float bias)
{
    #pragma unroll
    for (int j = 0; j < 16; j++) {
        float2 a = up2(acc[j]);
        int u = base + 2 * j;
        size_t adr = ((size_t)b * 1000 + t0 + u) * 512 + c * 128 + h;
        if (t0 + u < 1000)     g_pre[adr]       = a.x + bias;
        if (t0 + u + 1 < 1000) g_pre[adr + 512] = a.y + bias;
    }
}

__global__ void __launch_bounds__(256) k2_pre(
    const float* __restrict__ inp,
    const float* __restrict__ Wdgh, const float* __restrict__ bdgh,
    const float* __restrict__ Wxz,  const float* __restrict__ Wmz, const float* __restrict__ bmz,
    const float* __restrict__ Wxr,  const float* __restrict__ Wmr,
    const float* __restrict__ Wxh,  const float* __restrict__ Wmh, const float* __restrict__ bmh)
{
    extern __shared__ float sm_[];
    float* sx  = sm_;          // 64k x 64t
    float* sm2 = sx + 4096;
    float* sd  = sm2 + 4096;
    float* sW  = sd + 4096;    // 64 x 128
    const int t0 = blockIdx.x * 64, b = blockIdx.y;
    const int tid = threadIdx.x, h = tid & 127, base = (tid >> 7) * 32;

    for (int e = tid; e < 4096; e += 256) {
        int k = e >> 6, u = e & 63;
        int t = t0 + u;
        float xv = 0.f, mv = 0.f, dv = 0.f;
        if (t < 1000) {
            xv = g_ximp[((size_t)(b * 64) + k) * 1000 + t];
            size_t gb = ((size_t)(b * 3 * 64) + k) * 1000 + t;
            mv = inp[gb + 64 * 1000];
            dv = inp[gb + 2 * 64 * 1000];
        }
        sx[k * 64 + u] = xv; sm2[k * 64 + u] = mv; sd[k * 64 + u] = dv;
    }
    unsigned long long acc[16];

    // ---- c0: gammaH = exp(-relu(d@W_dg_h + b_dg_h)) ----
    for (int e = tid; e < 8192; e += 256) sW[e] = Wdgh[e];
    __syncthreads();
    #pragma unroll
    for (int j = 0; j < 16; j++) acc[j] = 0ull;
    gemm64(sd, sW, acc, h, base);
    {
        float bb = bdgh[h];
        #pragma unroll
        for (int j = 0; j < 16; j++) {
            float2 a = up2(acc[j]);
            int u = base + 2 * j;
            size_t adr = ((size_t)b * 1000 + t0 + u) * 512 + h;
            if (t0 + u < 1000)     g_pre[adr]       = __expf(-fmaxf(a.x + bb, 0.f));
            if (t0 + u + 1 < 1000) g_pre[adr + 512] = __expf(-fmaxf(a.y + bb, 0.f));
        }
    }
    // ---- c1: preZ = x@Wxz + m@Wmz + bmz ----
    __syncthreads();
    for (int e = tid; e < 8192; e += 256) sW[e] = Wxz[e];
    __syncthreads();
    #pragma unroll
    for (int j = 0; j < 16; j++) acc[j] = 0ull;
    gemm64(sx, sW, acc, h, base);
    __syncthreads();
    for (int e = tid; e < 8192; e += 256) sW[e] = Wmz[e];
    __syncthreads();
    gemm64(sm2, sW, acc, h, base);
    store_pre(acc, b, t0, base, h, 1, bmz[h]);

    // ---- c2: preR = x@Wxr + m@Wmr ----
    __syncthreads();
    for (int e = tid; e < 8192; e += 256) sW[e] = Wxr[e];
    __syncthreads();
    #pragma unroll
    for (int j = 0; j < 16; j++) acc[j] = 0ull;
    gemm64(sx, sW, acc, h, base);
    __syncthreads();
    for (int e = tid; e < 8192; e += 256) sW[e] = Wmr[e];
    __syncthreads();
    gemm64(sm2, sW, acc, h, base);
    store_pre(acc, b, t0, base, h, 2, 0.f);

    // ---- c3: preH = x@Wxh + m@Wmh + bmh ----
    __syncthreads();
    for (int e = tid; e < 8192; e += 256) sW[e] = Wxh[e];
    __syncthreads();
    #pragma unroll
    for (int j = 0; j < 16; j++) acc[j] = 0ull;
    gemm64(sx, sW, acc, h, base);
    __syncthreads();
    for (int e = tid; e < 8192; e += 256) sW[e] = Wmh[e];
    __syncthreads();
    gemm64(sm2, sW, acc, h, base);
    store_pre(acc, b, t0, base, h, 3, bmh[h]);
}

// ============================================================================
// K3: persistent-register recurrence. 128 CTAs x 256 threads, 2 batches/CTA.
// Weights W_hz/W_hr/W_hh live in registers (192 regs/thread). h broadcast via
// smem as duplicated f32x2 pairs. Partial sums reduced across 4 j-groups.
// ============================================================================
__global__ void __launch_bounds__(256, 1) k3_rec(
    const float* __restrict__ Whz, const float* __restrict__ Whr,
    const float* __restrict__ Whh, float* __restrict__ hs)
{
    __shared__ unsigned long long shd[2][128];    // gamma-scaled h, duplicated pairs
    __shared__ unsigned long long srhd[2][128];   // r*h, duplicated pairs
    __shared__ unsigned long long sred[4][256];   // partial sums

    const int tid = threadIdx.x;
    const int p = tid & 63, jg = tid >> 6;
    const int jbase = jg * 32;

    unsigned long long wz[32], wr[32], wh[32];
    #pragma unroll
    for (int j = 0; j < 32; j++) {
        int row = (jbase + j) * 128 + 2 * p;
        wz[j] = *(const unsigned long long*)(Whz + row);
        wr[j] = *(const unsigned long long*)(Whr + row);
        wh[j] = *(const unsigned long long*)(Whh + row);
    }

    const int b  = jg & 1;                        // valid for tid < 128
    const int bg = blockIdx.x * 2 + b;

    unsigned long long h2 = 0ull;                 // gamma-scaled h pair (reducers)
    unsigned long long cz = 0ull, cr = 0ull, ch = 0ull;
    float zx = 0.f, zy = 0.f;

    if (tid < 128) {
        shd[b][2 * p] = 0ull; shd[b][2 * p + 1] = 0ull;
        size_t adr = ((size_t)bg * 1000) * 512 + 2 * p;
        cz = *(const unsigned long long*)&g_pre[adr + 128];
        cr = *(const unsigned long long*)&g_pre[adr + 256];
        ch = *(const unsigned long long*)&g_pre[adr + 384];
    }
    __syncthreads();

    for (int t = 0; t < 1000; t++) {
        // prefetch next step's pre-activations
        unsigned long long ng = 0ull, nz = 0ull, nr = 0ull, nh = 0ull;
        if (tid < 128) {
            int tn = (t + 1 < 1000) ? t + 1 : 999;
            size_t adr = ((size_t)bg * 1000 + tn) * 512 + 2 * p;
            ng = *(const unsigned long long*)&g_pre[adr];
            nz = *(const unsigned long long*)&g_pre[adr + 128];
            nr = *(const unsigned long long*)&g_pre[adr + 256];
            nh = *(const unsigned long long*)&g_pre[adr + 384];
        }

        // ---- stage B: z/r partial dots ----
        unsigned long long az0 = 0, az1 = 0, ar0 = 0, ar1 = 0;
        #pragma unroll
        for (int j = 0; j < 32; j++) {
            unsigned long long h0 = shd[0][jbase + j];
            unsigned long long h1 = shd[1][jbase + j];
            fma2(az0, h0, wz[j]);
            fma2(ar0, h0, wr[j]);
            fma2(az1, h1, wz[j]);
            fma2(ar1, h1, wr[j]);
        }
        sred[0][tid] = az0; sred[1][tid] = az1; sred[2][tid] = ar0; sred[3][tid] = ar1;
        __syncthreads();

        if (tid < 128) {
            float2 zp = up2(cz), rp = up2(cr);
            zx = zp.x; zy = zp.y;
            float rx = rp.x, ry = rp.y;
            #pragma unroll
            for (int g = 0; g < 4; g++) {
                float2 a = up2(sred[b][g * 64 + p]);     zx += a.x; zy += a.y;
                float2 c = up2(sred[2 + b][g * 64 + p]); rx += c.x; ry += c.y;
            }
            zx = sigf(zx); zy = sigf(zy); rx = sigf(rx); ry = sigf(ry);
            float2 hv = up2(h2);
            float r0 = rx * hv.x, r1 = ry * hv.y;
            srhd[b][2 * p]     = pk2(r0, r0);
            srhd[b][2 * p + 1] = pk2(r1, r1);
        }
        __syncthreads();

        // ---- stage C: h_tilde partial dots ----
        unsigned long long ah0 = 0, ah1 = 0;
        #pragma unroll
        for (int j = 0; j < 32; j++) {
            fma2(ah0, srhd[0][jbase + j], wh[j]);
            fma2(ah1, srhd[1][jbase + j], wh[j]);
        }
        sred[0][tid] = ah0; sred[1][tid] = ah1;
        __syncthreads();

        if (tid < 128) {
            float2 hp = up2(ch);
            float hx = hp.x, hy = hp.y;
            #pragma unroll
            for (int g = 0; g < 4; g++) {
                float2 a = up2(sred[b][g * 64 + p]); hx += a.x; hy += a.y;
            }
            hx = tanhf_(hx); hy = tanhf_(hy);
            float2 hv = up2(h2);
            float h0n = (1.f - zx) * hv.x + zx * hx;
            float h1n = (1.f - zy) * hv.y + zy * hy;
            *(float2*)&hs[((size_t)bg * 1000 + t) * 128 + 2 * p] = make_float2(h0n, h1n);
            // apply NEXT step's gamma and publish
            float2 gg = up2(ng);
            float s0 = gg.x * h0n, s1 = gg.y * h1n;
            h2 = pk2(s0, s1);
            shd[b][2 * p]     = pk2(s0, s0);
            shd[b][2 * p + 1] = pk2(s1, s1);
            cz = nz; cr = nr; ch = nh;
        }
        __syncthreads();
    }
}

// ============================================================================
// K4: y = sigmoid(hs @ W_hy + b_hy). CTA = (t-tile 64, batch).
// ============================================================================
__global__ void __launch_bounds__(256) k4_out(
    const float* __restrict__ hs, const float* __restrict__ Why,
    const float* __restrict__ bhy, float* __restrict__ ys)
{
    extern __shared__ float sm_[];
    float* sh = sm_;            // [tt][h] 64 x 128
    float* sW = sh + 8192;      // 128 x 64
    const int t0 = blockIdx.x * 64, b = blockIdx.y;
    const int tid = threadIdx.x;

    for (int e = tid; e < 8192; e += 256) sW[e] = Why[e];
    for (int e = tid; e < 8192; e += 256) {
        int tt = e >> 7, h = e & 127;
        int t = t0 + tt;
        sh[e] = (t < 1000) ? hs[((size_t)b * 1000 + t) * 128 + h] : 0.f;
    }
    __syncthreads();

    const int o = tid & 63, q = tid >> 6;   // q in [0,4), 16 t each
    float acc[16];
    #pragma unroll
    for (int j = 0; j < 16; j++) acc[j] = 0.f;
    for (int h = 0; h < 128; h++) {
        float w = sW[h * 64 + o];
        #pragma unroll
        for (int j = 0; j < 16; j++) acc[j] += sh[(q * 16 + j) * 128 + h] * w;
    }
    float bb = bhy[o];
    #pragma unroll
    for (int j = 0; j < 16; j++) {
        int t = t0 + q * 16 + j;
        if (t < 1000) ys[((size_t)b * 1000 + t) * 64 + o] = sigf(acc[j] + bb);
    }
}

// ============================================================================
extern "C" void kernel_launch(void* const* d_in, const int* in_sizes, int n_in,
                              void* d_out, int out_size)
{
    const float* inp   = (const float*)d_in[0];
    const float* xmean = (const float*)d_in[1];
    const float* Wdgx  = (const float*)d_in[2];
    const float* bdgx  = (const float*)d_in[3];
    const float* Wdgh  = (const float*)d_in[4];
    const float* bdgh  = (const float*)d_in[5];
    const float* Wxz   = (const float*)d_in[6];
    const float* Whz   = (const float*)d_in[7];
    const float* Wmz   = (const float*)d_in[8];
    const float* bmz   = (const float*)d_in[9];
    const float* Wxr   = (const float*)d_in[10];
    const float* Whr   = (const float*)d_in[11];
    const float* Wmr   = (const float*)d_in[12];
    const float* Wxh   = (const float*)d_in[13];
    const float* Whh   = (const float*)d_in[14];
    const float* Wmh   = (const float*)d_in[15];
    const float* bmh   = (const float*)d_in[16];
    const float* Why   = (const float*)d_in[17];
    const float* bhy   = (const float*)d_in[18];

    float* ys = (float*)d_out;                        // (B,T,64)
    float* hs = ys + (size_t)256 * 1000 * 64;         // (B,T,128)

    const int K1_SMEM = (4 * 64 * 129 + 64 * 64) * 4;     // 148480 B
    const int K2_SMEM = (3 * 4096 + 8192) * 4;            // 81920 B
    const int K4_SMEM = (8192 + 8192) * 4;                // 65536 B
    cudaFuncSetAttribute(k1_impute, cudaFuncAttributeMaxDynamicSharedMemorySize, K1_SMEM);
    cudaFuncSetAttribute(k2_pre,    cudaFuncAttributeMaxDynamicSharedMemorySize, K2_SMEM);
    cudaFuncSetAttribute(k4_out,    cudaFuncAttributeMaxDynamicSharedMemorySize, K4_SMEM);

    k1_impute<<<256, 256, K1_SMEM>>>(inp, xmean, Wdgx, bdgx);

    dim3 g2(16, 256);
    k2_pre<<<g2, 256, K2_SMEM>>>(inp, Wdgh, bdgh, Wxz, Wmz, bmz, Wxr, Wmr, Wxh, Wmh, bmh);

    k3_rec<<<128, 256>>>(Whz, Whr, Whh, hs);

    dim3 g4(16, 256);
    k4_out<<<g4, 256, K4_SMEM>>>(hs, Why, bhy, ys);
}